// round 2
// baseline (speedup 1.0000x reference)
#include <cuda_runtime.h>
#include <cuda_bf16.h>
#include <math_constants.h>

#define N_NODES   50000
#define N_EDGES   1600000
#define IN_H      256
#define OUT_H     32
#define NHEAD     4
#define HDIM      128     // NHEAD*OUT_H
#define EDGE_H    64
#define N_ETYPES  8
#define NEG_SLOPE 0.2f

// ---------------- scratch (static device allocations are the sanctioned way) ----
__device__ __align__(16) float g_h[N_NODES * HDIM];        // projected node features
__device__ __align__(16) float g_hl[N_NODES * NHEAD];
__device__ __align__(16) float g_hr[N_NODES * NHEAD];
__device__ __align__(16) float g_he[N_ETYPES * NHEAD];
__device__ __align__(16) float g_denom[N_NODES * NHEAD];
__device__ int      g_counts[N_NODES + 1];
__device__ int      g_offsets[N_NODES + 1];
__device__ int      g_cursor[N_NODES];
__device__ int      g_esorted[N_EDGES];
__device__ int      g_ssorted[N_EDGES];
__device__ unsigned g_maxbits;

// monotone float<->uint encoding for atomicMax over signed floats
__device__ __forceinline__ unsigned enc_f(float f) {
    unsigned u = __float_as_uint(f);
    return (u & 0x80000000u) ? ~u : (u | 0x80000000u);
}
__device__ __forceinline__ float dec_f(unsigned u) {
    return (u & 0x80000000u) ? __uint_as_float(u & 0x7FFFFFFFu)
                             : __uint_as_float(~u);
}

// ---------------- K0: zero scratch ------------------------------------------------
__global__ void k_zero() {
    int i = blockIdx.x * blockDim.x + threadIdx.x;
    if (i < N_NODES * NHEAD) g_denom[i] = 0.0f;
    if (i <= N_NODES)        g_counts[i] = 0;
    if (i == 0)              g_maxbits = 0u;   // 0 is below every valid encoding
}

// ---------------- K1: h = nan_clean(x @ W) ---------------------------------------
// BM=64 rows, full N=128 cols, BK=32. 256 threads: 8 rows x 4 cols each.
__global__ __launch_bounds__(256) void k_gemm(const float* __restrict__ x,
                                              const float* __restrict__ W) {
    __shared__ float  xs[64][32];
    __shared__ float4 ws[32][32];   // ws[kk][c4] -> cols c4*4..c4*4+3
    const int t  = threadIdx.x;
    const int tx = t & 31;          // col group
    const int ty = t >> 5;          // 0..7
    const int row0 = blockIdx.x * 64;

    float acc[8][4];
#pragma unroll
    for (int r = 0; r < 8; r++)
#pragma unroll
        for (int c = 0; c < 4; c++) acc[r][c] = 0.0f;

    for (int k0 = 0; k0 < IN_H; k0 += 32) {
#pragma unroll
        for (int i = 0; i < 2; i++) {             // 512 float4 x-loads
            int i4 = t + i * 256;
            int r = i4 >> 3, kk4 = i4 & 7;
            int row = row0 + r;
            float4 v = make_float4(0.f, 0.f, 0.f, 0.f);
            if (row < N_NODES)
                v = *(const float4*)(x + (size_t)row * IN_H + k0 + kk4 * 4);
            ((float4*)&xs[r][0])[kk4] = v;
        }
#pragma unroll
        for (int i = 0; i < 4; i++) {             // 1024 float4 W-loads
            int i4 = t + i * 256;
            int kk = i4 >> 5, c4 = i4 & 31;
            ws[kk][c4] = *(const float4*)(W + (size_t)(k0 + kk) * HDIM + c4 * 4);
        }
        __syncthreads();
#pragma unroll
        for (int kk = 0; kk < 32; kk++) {
            float4 wv = ws[kk][tx];
#pragma unroll
            for (int rr = 0; rr < 8; rr++) {
                float xv = xs[ty + rr * 8][kk];
                acc[rr][0] += xv * wv.x;
                acc[rr][1] += xv * wv.y;
                acc[rr][2] += xv * wv.z;
                acc[rr][3] += xv * wv.w;
            }
        }
        __syncthreads();
    }
#pragma unroll
    for (int rr = 0; rr < 8; rr++) {
        int row = row0 + ty + rr * 8;
        if (row < N_NODES) {
            float4 v;
            v.x = (acc[rr][0] == acc[rr][0]) ? acc[rr][0] : 0.0f;
            v.y = (acc[rr][1] == acc[rr][1]) ? acc[rr][1] : 0.0f;
            v.z = (acc[rr][2] == acc[rr][2]) ? acc[rr][2] : 0.0f;
            v.w = (acc[rr][3] == acc[rr][3]) ? acc[rr][3] : 0.0f;
            *(float4*)(g_h + (size_t)row * HDIM + tx * 4) = v;
        }
    }
}

// ---------------- K2: hl/hr = (a_l*h).sum(-1), (a_r*h).sum(-1) -------------------
__global__ void k_hlr(const float* __restrict__ a_l, const float* __restrict__ a_r) {
    int gw   = (blockIdx.x * blockDim.x + threadIdx.x) >> 5;
    int lane = threadIdx.x & 31;
    if (gw >= N_NODES) return;
    float pl[NHEAD], pr[NHEAD];
#pragma unroll
    for (int hh = 0; hh < NHEAD; hh++) {
        float v  = g_h[(size_t)gw * HDIM + hh * OUT_H + lane];
        pl[hh] = v * a_l[hh * OUT_H + lane];
        pr[hh] = v * a_r[hh * OUT_H + lane];
    }
#pragma unroll
    for (int o = 16; o > 0; o >>= 1) {
#pragma unroll
        for (int hh = 0; hh < NHEAD; hh++) {
            pl[hh] += __shfl_xor_sync(0xFFFFFFFFu, pl[hh], o);
            pr[hh] += __shfl_xor_sync(0xFFFFFFFFu, pr[hh], o);
        }
    }
    if (lane == 0) {
        *(float4*)(g_hl + gw * 4) = make_float4(pl[0], pl[1], pl[2], pl[3]);
        *(float4*)(g_hr + gw * 4) = make_float4(pr[0], pr[1], pr[2], pr[3]);
    }
}

// ---------------- K3: he[t,h] = (a_e * (edge_emb @ W_e)).sum(-1) ------------------
__global__ void k_he(const float* __restrict__ edge_emb, const float* __restrict__ W_e,
                     const float* __restrict__ a_e) {
    int t    = threadIdx.x;
    int ti   = t >> 5;        // edge type, warp per type (8 warps = 256 threads)
    int lane = t & 31;
    float res[NHEAD] = {0.f, 0.f, 0.f, 0.f};
#pragma unroll
    for (int hh = 0; hh < NHEAD; hh++) {
        for (int half = 0; half < 2; half++) {
            int de = lane + half * 32;
            float p = 0.f;
#pragma unroll 8
            for (int k = 0; k < EDGE_H; k++)
                p += edge_emb[ti * EDGE_H + k] * W_e[k * (EDGE_H * NHEAD) + hh * EDGE_H + de];
            res[hh] += p * a_e[hh * EDGE_H + de];
        }
    }
#pragma unroll
    for (int o = 16; o > 0; o >>= 1)
#pragma unroll
        for (int hh = 0; hh < NHEAD; hh++)
            res[hh] += __shfl_xor_sync(0xFFFFFFFFu, res[hh], o);
    if (lane == 0)
#pragma unroll
        for (int hh = 0; hh < NHEAD; hh++) g_he[ti * NHEAD + hh] = res[hh];
}

// ---------------- K4: scores + histogram + global max -----------------------------
__global__ void k_edge_score(const int* __restrict__ edge, float* __restrict__ attn) {
    __shared__ float wmax[8];
    int e = blockIdx.x * blockDim.x + threadIdx.x;
    float m = -CUDART_INF_F;
    if (e < N_EDGES) {
        int s  = edge[e];
        int tg = edge[N_EDGES + e];
        int ty = edge[2 * N_EDGES + e];
        float4 hl = *(const float4*)(g_hl + s * 4);
        float4 hr = *(const float4*)(g_hr + tg * 4);
        float4 he = *(const float4*)(g_he + ty * 4);
        float4 sc;
        sc.x = hl.x + hr.x + he.x;  sc.x = sc.x > 0.f ? sc.x : NEG_SLOPE * sc.x;
        sc.y = hl.y + hr.y + he.y;  sc.y = sc.y > 0.f ? sc.y : NEG_SLOPE * sc.y;
        sc.z = hl.z + hr.z + he.z;  sc.z = sc.z > 0.f ? sc.z : NEG_SLOPE * sc.z;
        sc.w = hl.w + hr.w + he.w;  sc.w = sc.w > 0.f ? sc.w : NEG_SLOPE * sc.w;
        *(float4*)(attn + (size_t)e * 4) = sc;
        atomicAdd(&g_counts[tg], 1);
        m = fmaxf(fmaxf(sc.x, sc.y), fmaxf(sc.z, sc.w));
    }
#pragma unroll
    for (int o = 16; o > 0; o >>= 1)
        m = fmaxf(m, __shfl_xor_sync(0xFFFFFFFFu, m, o));
    int wid = threadIdx.x >> 5;
    if ((threadIdx.x & 31) == 0) wmax[wid] = m;
    __syncthreads();
    if (threadIdx.x == 0) {
        float bm = wmax[0];
#pragma unroll
        for (int i = 1; i < 8; i++) bm = fmaxf(bm, wmax[i]);
        atomicMax(&g_maxbits, enc_f(bm));
    }
}

// ---------------- K5: exclusive scan of counts -> offsets/cursor ------------------
__global__ void k_scan() {
    const int C = (N_NODES + 1023) / 1024;   // 49
    __shared__ int ssum[1024];
    int t = threadIdx.x;
    int beg = t * C;
    int end = min(beg + C, N_NODES);
    int local = 0;
    for (int i = beg; i < end; i++) local += g_counts[i];
    ssum[t] = local;
    __syncthreads();
    for (int d = 1; d < 1024; d <<= 1) {
        int v = (t >= d) ? ssum[t - d] : 0;
        __syncthreads();
        ssum[t] += v;
        __syncthreads();
    }
    int run = (t == 0) ? 0 : ssum[t - 1];
    for (int i = beg; i < end; i++) {
        g_offsets[i] = run;
        g_cursor[i]  = run;
        run += g_counts[i];
    }
    if (t == 1023) g_offsets[N_NODES] = ssum[1023];
}

// ---------------- K6: exp + denom atomics + CSR scatter ---------------------------
__global__ void k_edge_exp(const int* __restrict__ edge, float* __restrict__ attn) {
    int e = blockIdx.x * blockDim.x + threadIdx.x;
    if (e >= N_EDGES) return;
    float gmax = dec_f(g_maxbits);
    int s  = edge[e];
    int tg = edge[N_EDGES + e];
    float4 sc = *(const float4*)(attn + (size_t)e * 4);
    float4 ex;
    ex.x = expf(sc.x - gmax);
    ex.y = expf(sc.y - gmax);
    ex.z = expf(sc.z - gmax);
    ex.w = expf(sc.w - gmax);
    *(float4*)(attn + (size_t)e * 4) = ex;
    atomicAdd(&g_denom[tg * 4 + 0], ex.x);
    atomicAdd(&g_denom[tg * 4 + 1], ex.y);
    atomicAdd(&g_denom[tg * 4 + 2], ex.z);
    atomicAdd(&g_denom[tg * 4 + 3], ex.w);
    int pos = atomicAdd(&g_cursor[tg], 1);
    g_esorted[pos] = e;
    g_ssorted[pos] = s;
}

// ---------------- K7: attn = exp / (denom[trg] + eps) (in place) ------------------
__global__ void k_attn_fin(const int* __restrict__ edge, float* __restrict__ attn) {
    int e = blockIdx.x * blockDim.x + threadIdx.x;
    if (e >= N_EDGES) return;
    int tg = edge[N_EDGES + e];
    float4 ex = *(const float4*)(attn + (size_t)e * 4);
    float4 dn = *(const float4*)(g_denom + tg * 4);
    ex.x = ex.x / (dn.x + 1e-16f);
    ex.y = ex.y / (dn.y + 1e-16f);
    ex.z = ex.z / (dn.z + 1e-16f);
    ex.w = ex.w / (dn.w + 1e-16f);
    *(float4*)(attn + (size_t)e * 4) = ex;
}

// ---------------- K8: CSR aggregation, warp per target node -----------------------
__global__ void k_agg(const float* __restrict__ attn, float* __restrict__ out) {
    int gw   = (blockIdx.x * blockDim.x + threadIdx.x) >> 5;
    int lane = threadIdx.x & 31;
    if (gw >= N_NODES) return;
    int beg = g_offsets[gw];
    int end = g_offsets[gw + 1];
    float a0 = 0.f, a1 = 0.f, a2 = 0.f, a3 = 0.f;
    const float4* attn4 = (const float4*)attn;
    for (int i = beg; i < end; i++) {
        int e = g_esorted[i];
        int s = g_ssorted[i];
        float4 a = __ldg(attn4 + e);
        const float* hp = g_h + (size_t)s * HDIM + lane;
        a0 += a.x * hp[0];
        a1 += a.y * hp[32];
        a2 += a.z * hp[64];
        a3 += a.w * hp[96];
    }
    float* op = out + (size_t)gw * HDIM + lane;
    op[0]  = a0;
    op[32] = a1;
    op[64] = a2;
    op[96] = a3;
}

// ---------------- launch ----------------------------------------------------------
extern "C" void kernel_launch(void* const* d_in, const int* in_sizes, int n_in,
                              void* d_out, int out_size) {
    const int*   edge     = (const int*)d_in[0];
    const float* x        = (const float*)d_in[1];
    const float* edge_emb = (const float*)d_in[2];
    const float* W        = (const float*)d_in[3];
    const float* W_e      = (const float*)d_in[4];
    const float* a_l      = (const float*)d_in[5];
    const float* a_r      = (const float*)d_in[6];
    const float* a_e      = (const float*)d_in[7];
    float* out  = (float*)d_out;
    float* attn = out + (size_t)N_NODES * HDIM;   // second output region

    (void)in_sizes; (void)n_in; (void)out_size;

    k_zero<<<(N_NODES * NHEAD + 255) / 256, 256>>>();
    k_gemm<<<(N_NODES + 63) / 64, 256>>>(x, W);
    k_hlr<<<(N_NODES * 32 + 255) / 256, 256>>>(a_l, a_r);
    k_he<<<1, 256>>>(edge_emb, W_e, a_e);
    k_edge_score<<<N_EDGES / 256, 256>>>(edge, attn);
    k_scan<<<1, 1024>>>();
    k_edge_exp<<<N_EDGES / 256, 256>>>(edge, attn);
    k_attn_fin<<<N_EDGES / 256, 256>>>(edge, attn);
    k_agg<<<(N_NODES * 32 + 255) / 256, 256>>>(attn, out);
}

// round 3
// speedup vs baseline: 1.0594x; 1.0594x over previous
#include <cuda_runtime.h>
#include <cuda_bf16.h>
#include <math_constants.h>

#define N_NODES   50000
#define N_EDGES   1600000
#define IN_H      256
#define OUT_H     32
#define NHEAD     4
#define HDIM      128     // NHEAD*OUT_H
#define EDGE_H    64
#define N_ETYPES  8
#define NEG_SLOPE 0.2f

typedef unsigned long long ull;

// ---------------- scratch ---------------------------------------------------------
__device__ __align__(16) float g_h[N_NODES * HDIM];          // projected node features
__device__ __align__(16) float g_hl[N_NODES * NHEAD];
__device__ __align__(16) float g_hr[N_NODES * NHEAD];
__device__ __align__(16) float g_he[N_ETYPES * NHEAD];
__device__ __align__(16) float4 g_exps[N_EDGES];             // exp scores in CSR order
__device__ int      g_counts[N_NODES + 1];
__device__ int      g_offsets[N_NODES + 1];
__device__ int      g_cursor[N_NODES];
__device__ int      g_ssorted[N_EDGES];                      // src in CSR order
__device__ int      g_eorig[N_EDGES];                        // original edge id in CSR order
__device__ unsigned g_maxhl, g_maxhr, g_maxhe;

// monotone float<->uint encoding for atomicMax over signed floats
__device__ __forceinline__ unsigned enc_f(float f) {
    unsigned u = __float_as_uint(f);
    return (u & 0x80000000u) ? ~u : (u | 0x80000000u);
}
__device__ __forceinline__ float dec_f(unsigned u) {
    return (u & 0x80000000u) ? __uint_as_float(u & 0x7FFFFFFFu)
                             : __uint_as_float(~u);
}

#define FMA2(d, a, b) asm("fma.rn.f32x2 %0, %1, %2, %0;" : "+l"(d) : "l"(a), "l"(b))
#define PACK2(p, v)   asm("mov.b64 %0, {%1, %2};" : "=l"(p) : "f"(v), "f"(v))
#define UNPACK2(lo, hi, p) asm("mov.b64 {%0, %1}, %2;" : "=f"(lo), "=f"(hi) : "l"(p))

// ---------------- K0: zero scratch ------------------------------------------------
__global__ void k_zero() {
    int i = blockIdx.x * blockDim.x + threadIdx.x;
    if (i <= N_NODES) g_counts[i] = 0;
    if (i == 0) { g_maxhl = 0u; g_maxhr = 0u; g_maxhe = 0u; }
}

// ---------------- K1: histogram of targets ---------------------------------------
__global__ void k_count(const int* __restrict__ edge) {
    int e = blockIdx.x * blockDim.x + threadIdx.x;
    if (e < N_EDGES) atomicAdd(&g_counts[edge[N_EDGES + e]], 1);
}

// ---------------- K2: h = nan_clean(x @ W), packed f32x2 FMA ----------------------
// BM=128 rows, BN=128 cols (all), BK=16. 256 threads, 8x8 register tile each.
__global__ __launch_bounds__(256, 2) void k_gemm(const float* __restrict__ x,
                                                 const float* __restrict__ W) {
    __shared__ ull   xs2[128][16];   // x value duplicated into both f32x2 lanes
    __shared__ float ws[16][128];
    const int t  = threadIdx.x;
    const int tx = t & 15;           // col group: cols tx*8 .. tx*8+7
    const int ty = t >> 4;           // 0..15: rows ty + 16*rr
    const int row0 = blockIdx.x * 128;

    ull acc[8][4];
#pragma unroll
    for (int r = 0; r < 8; r++)
#pragma unroll
        for (int c = 0; c < 4; c++) acc[r][c] = 0ull;

    for (int k0 = 0; k0 < IN_H; k0 += 16) {
#pragma unroll
        for (int i = 0; i < 2; i++) {              // 512 float4 x-loads
            int i4 = t + i * 256;
            int r = i4 >> 2, kk4 = i4 & 3;
            int row = row0 + r;
            float4 v = make_float4(0.f, 0.f, 0.f, 0.f);
            if (row < N_NODES)
                v = *(const float4*)(x + (size_t)row * IN_H + k0 + kk4 * 4);
            ull p0, p1, p2, p3;
            PACK2(p0, v.x); PACK2(p1, v.y); PACK2(p2, v.z); PACK2(p3, v.w);
            xs2[r][kk4 * 4 + 0] = p0;
            xs2[r][kk4 * 4 + 1] = p1;
            xs2[r][kk4 * 4 + 2] = p2;
            xs2[r][kk4 * 4 + 3] = p3;
        }
#pragma unroll
        for (int i = 0; i < 2; i++) {              // 512 float4 W-loads
            int i4 = t + i * 256;
            int kk = i4 >> 5, c4 = i4 & 31;
            *(float4*)&ws[kk][c4 * 4] = *(const float4*)(W + (size_t)(k0 + kk) * HDIM + c4 * 4);
        }
        __syncthreads();
#pragma unroll
        for (int kk = 0; kk < 16; kk++) {
            ull b0 = ((const ull*)&ws[kk][0])[tx * 4 + 0];
            ull b1 = ((const ull*)&ws[kk][0])[tx * 4 + 1];
            ull b2 = ((const ull*)&ws[kk][0])[tx * 4 + 2];
            ull b3 = ((const ull*)&ws[kk][0])[tx * 4 + 3];
#pragma unroll
            for (int rr = 0; rr < 8; rr++) {
                ull ax = xs2[ty + 16 * rr][kk];
                FMA2(acc[rr][0], ax, b0);
                FMA2(acc[rr][1], ax, b1);
                FMA2(acc[rr][2], ax, b2);
                FMA2(acc[rr][3], ax, b3);
            }
        }
        __syncthreads();
    }
#pragma unroll
    for (int rr = 0; rr < 8; rr++) {
        int row = row0 + ty + 16 * rr;
        if (row < N_NODES) {
            float v[8];
#pragma unroll
            for (int j = 0; j < 4; j++) UNPACK2(v[2 * j], v[2 * j + 1], acc[rr][j]);
#pragma unroll
            for (int j = 0; j < 8; j++) v[j] = (v[j] == v[j]) ? v[j] : 0.0f;
            *(float4*)(g_h + (size_t)row * HDIM + tx * 8)     = make_float4(v[0], v[1], v[2], v[3]);
            *(float4*)(g_h + (size_t)row * HDIM + tx * 8 + 4) = make_float4(v[4], v[5], v[6], v[7]);
        }
    }
}

// ---------------- K3: hl/hr = (a_l*h).sum(-1), (a_r*h).sum(-1) + maxes ------------
__global__ void k_hlr(const float* __restrict__ a_l, const float* __restrict__ a_r) {
    __shared__ float smax[16];
    int gw   = (blockIdx.x * blockDim.x + threadIdx.x) >> 5;
    int lane = threadIdx.x & 31;
    int wid  = threadIdx.x >> 5;
    float ml = -CUDART_INF_F, mr = -CUDART_INF_F;
    if (gw < N_NODES) {
        float pl[NHEAD], pr[NHEAD];
#pragma unroll
        for (int hh = 0; hh < NHEAD; hh++) {
            float v  = g_h[(size_t)gw * HDIM + hh * OUT_H + lane];
            pl[hh] = v * a_l[hh * OUT_H + lane];
            pr[hh] = v * a_r[hh * OUT_H + lane];
        }
#pragma unroll
        for (int o = 16; o > 0; o >>= 1) {
#pragma unroll
            for (int hh = 0; hh < NHEAD; hh++) {
                pl[hh] += __shfl_xor_sync(0xFFFFFFFFu, pl[hh], o);
                pr[hh] += __shfl_xor_sync(0xFFFFFFFFu, pr[hh], o);
            }
        }
        if (lane == 0) {
            *(float4*)(g_hl + gw * 4) = make_float4(pl[0], pl[1], pl[2], pl[3]);
            *(float4*)(g_hr + gw * 4) = make_float4(pr[0], pr[1], pr[2], pr[3]);
            ml = fmaxf(fmaxf(pl[0], pl[1]), fmaxf(pl[2], pl[3]));
            mr = fmaxf(fmaxf(pr[0], pr[1]), fmaxf(pr[2], pr[3]));
        }
    }
    // block-reduce maxes (lane0 of each warp holds real values)
    if (lane == 0) { smax[wid] = ml; smax[8 + wid] = mr; }
    __syncthreads();
    if (threadIdx.x == 0) {
        float bl = smax[0], br = smax[8];
#pragma unroll
        for (int i = 1; i < 8; i++) { bl = fmaxf(bl, smax[i]); br = fmaxf(br, smax[8 + i]); }
        if (bl == bl && bl > -CUDART_INF_F) atomicMax(&g_maxhl, enc_f(bl));
        if (br == br && br > -CUDART_INF_F) atomicMax(&g_maxhr, enc_f(br));
    }
}

// ---------------- K4: he[t,h] = (a_e * (edge_emb @ W_e)).sum(-1) + max ------------
// 32 blocks (type*4+head), 64 threads (one per de).
__global__ void k_he(const float* __restrict__ edge_emb, const float* __restrict__ W_e,
                     const float* __restrict__ a_e) {
    __shared__ float emb[EDGE_H];
    __shared__ float part[2];
    int ti = blockIdx.x >> 2;
    int hh = blockIdx.x & 3;
    int de = threadIdx.x;
    if (de < EDGE_H) emb[de] = edge_emb[ti * EDGE_H + de];
    __syncthreads();
    float p = 0.f;
#pragma unroll 8
    for (int k = 0; k < EDGE_H; k++)
        p += emb[k] * W_e[k * (EDGE_H * NHEAD) + hh * EDGE_H + de];
    float v = p * a_e[hh * EDGE_H + de];
#pragma unroll
    for (int o = 16; o > 0; o >>= 1)
        v += __shfl_xor_sync(0xFFFFFFFFu, v, o);
    if ((de & 31) == 0) part[de >> 5] = v;
    __syncthreads();
    if (de == 0) {
        float r = part[0] + part[1];
        g_he[ti * NHEAD + hh] = r;
        atomicMax(&g_maxhe, enc_f(r));
    }
}

// ---------------- K5: exclusive scan of counts -> offsets/cursor ------------------
__global__ void k_scan() {
    const int C = (N_NODES + 1023) / 1024;
    __shared__ int ssum[1024];
    int t = threadIdx.x;
    int beg = t * C;
    int end = min(beg + C, N_NODES);
    int local = 0;
    for (int i = beg; i < end; i++) local += g_counts[i];
    ssum[t] = local;
    __syncthreads();
    for (int d = 1; d < 1024; d <<= 1) {
        int v = (t >= d) ? ssum[t - d] : 0;
        __syncthreads();
        ssum[t] += v;
        __syncthreads();
    }
    int run = (t == 0) ? 0 : ssum[t - 1];
    for (int i = beg; i < end; i++) {
        g_offsets[i] = run;
        g_cursor[i]  = run;
        run += g_counts[i];
    }
    if (t == 1023) g_offsets[N_NODES] = ssum[1023];
}

// ---------------- K6: fused score + exp + CSR scatter -----------------------------
// softmax shift uses upper bound M = max(hl)+max(hr)+max(he); shift-invariant.
__global__ void k_edge(const int* __restrict__ edge) {
    int e = blockIdx.x * blockDim.x + threadIdx.x;
    if (e >= N_EDGES) return;
    float M = dec_f(g_maxhl) + dec_f(g_maxhr) + dec_f(g_maxhe);
    int s  = edge[e];
    int tg = edge[N_EDGES + e];
    int ty = edge[2 * N_EDGES + e];
    float4 hl = *(const float4*)(g_hl + s * 4);
    float4 hr = *(const float4*)(g_hr + tg * 4);
    float4 he = *(const float4*)(g_he + ty * 4);
    float4 sc;
    sc.x = hl.x + hr.x + he.x;  sc.x = sc.x > 0.f ? sc.x : NEG_SLOPE * sc.x;
    sc.y = hl.y + hr.y + he.y;  sc.y = sc.y > 0.f ? sc.y : NEG_SLOPE * sc.y;
    sc.z = hl.z + hr.z + he.z;  sc.z = sc.z > 0.f ? sc.z : NEG_SLOPE * sc.z;
    sc.w = hl.w + hr.w + he.w;  sc.w = sc.w > 0.f ? sc.w : NEG_SLOPE * sc.w;
    float4 ex;
    ex.x = expf(sc.x - M);
    ex.y = expf(sc.y - M);
    ex.z = expf(sc.z - M);
    ex.w = expf(sc.w - M);
    int pos = atomicAdd(&g_cursor[tg], 1);
    g_exps[pos]    = ex;
    g_ssorted[pos] = s;
    g_eorig[pos]   = e;
}

// ---------------- K7: CSR aggregation + softmax denom + attn write ----------------
// warp per target node; denom computed locally (no atomics), attn normalized here.
__global__ void k_agg(float* __restrict__ out, float* __restrict__ attn) {
    int gw   = (blockIdx.x * blockDim.x + threadIdx.x) >> 5;
    int lane = threadIdx.x & 31;
    if (gw >= N_NODES) return;
    int beg = g_offsets[gw];
    int end = g_offsets[gw + 1];

    // pass 1: denominator (lanes stride over edges, coalesced)
    float4 dsum = make_float4(0.f, 0.f, 0.f, 0.f);
    for (int i = beg + lane; i < end; i += 32) {
        float4 ex = g_exps[i];
        dsum.x += ex.x; dsum.y += ex.y; dsum.z += ex.z; dsum.w += ex.w;
    }
#pragma unroll
    for (int o = 16; o > 0; o >>= 1) {
        dsum.x += __shfl_xor_sync(0xFFFFFFFFu, dsum.x, o);
        dsum.y += __shfl_xor_sync(0xFFFFFFFFu, dsum.y, o);
        dsum.z += __shfl_xor_sync(0xFFFFFFFFu, dsum.z, o);
        dsum.w += __shfl_xor_sync(0xFFFFFFFFu, dsum.w, o);
    }
    float4 inv;
    inv.x = 1.0f / (dsum.x + 1e-16f);
    inv.y = 1.0f / (dsum.y + 1e-16f);
    inv.z = 1.0f / (dsum.z + 1e-16f);
    inv.w = 1.0f / (dsum.w + 1e-16f);

    // pass 2: normalize + scatter attn + accumulate messages
    float a0 = 0.f, a1 = 0.f, a2 = 0.f, a3 = 0.f;
    for (int i = beg; i < end; i++) {
        float4 ex = g_exps[i];
        int s = g_ssorted[i];
        float4 a;
        a.x = ex.x * inv.x;
        a.y = ex.y * inv.y;
        a.z = ex.z * inv.z;
        a.w = ex.w * inv.w;
        if (lane == 0) {
            int e = g_eorig[i];
            *(float4*)(attn + (size_t)e * 4) = a;
        }
        const float* hp = g_h + (size_t)s * HDIM + lane;
        a0 += a.x * hp[0];
        a1 += a.y * hp[32];
        a2 += a.z * hp[64];
        a3 += a.w * hp[96];
    }
    float* op = out + (size_t)gw * HDIM + lane;
    op[0]  = a0;
    op[32] = a1;
    op[64] = a2;
    op[96] = a3;
}

// ---------------- launch ----------------------------------------------------------
extern "C" void kernel_launch(void* const* d_in, const int* in_sizes, int n_in,
                              void* d_out, int out_size) {
    const int*   edge     = (const int*)d_in[0];
    const float* x        = (const float*)d_in[1];
    const float* edge_emb = (const float*)d_in[2];
    const float* W        = (const float*)d_in[3];
    const float* W_e      = (const float*)d_in[4];
    const float* a_l      = (const float*)d_in[5];
    const float* a_r      = (const float*)d_in[6];
    const float* a_e      = (const float*)d_in[7];
    float* out  = (float*)d_out;
    float* attn = out + (size_t)N_NODES * HDIM;

    (void)in_sizes; (void)n_in; (void)out_size;

    k_zero <<<(N_NODES + 256) / 256, 256>>>();
    k_count<<<N_EDGES / 256, 256>>>(edge);
    k_gemm <<<(N_NODES + 127) / 128, 256>>>(x, W);
    k_hlr  <<<(N_NODES * 32 + 255) / 256, 256>>>(a_l, a_r);
    k_he   <<<N_ETYPES * NHEAD, EDGE_H>>>(edge_emb, W_e, a_e);
    k_scan <<<1, 1024>>>();
    k_edge <<<N_EDGES / 256, 256>>>(edge);
    k_agg  <<<(N_NODES * 32 + 255) / 256, 256>>>(out, attn);
}

// round 4
// speedup vs baseline: 1.2654x; 1.1945x over previous
#include <cuda_runtime.h>
#include <cuda_bf16.h>
#include <math_constants.h>

#define N_NODES   50000
#define N_EDGES   1600000
#define IN_H      256
#define OUT_H     32
#define NHEAD     4
#define HDIM      128     // NHEAD*OUT_H
#define EDGE_H    64
#define N_ETYPES  8
#define NEG_SLOPE 0.2f

typedef unsigned long long ull;

// ---------------- scratch ---------------------------------------------------------
__device__ __align__(16) float  g_h[N_NODES * HDIM];     // projected node features
__device__ __align__(16) float  g_hl[N_NODES * NHEAD];
__device__ __align__(16) float  g_hr[N_NODES * NHEAD];
__device__ __align__(16) float  g_he[N_ETYPES * NHEAD];
__device__ __align__(16) float4 g_exps[N_EDGES];         // exp scores in CSR order
__device__ __align__(16) float4 g_inv[N_NODES];          // 1/denom per node
__device__ int      g_counts[N_NODES + 1];
__device__ int      g_offsets[N_NODES + 1];
__device__ int      g_cursor[N_NODES];
__device__ int      g_ssorted[N_EDGES];                  // src in CSR order
__device__ unsigned g_maxhl, g_maxhr, g_maxhe;

// monotone float<->uint encoding for atomicMax over signed floats
__device__ __forceinline__ unsigned enc_f(float f) {
    unsigned u = __float_as_uint(f);
    return (u & 0x80000000u) ? ~u : (u | 0x80000000u);
}
__device__ __forceinline__ float dec_f(unsigned u) {
    return (u & 0x80000000u) ? __uint_as_float(u & 0x7FFFFFFFu)
                             : __uint_as_float(~u);
}

#define FMA2(d, a, b) asm("fma.rn.f32x2 %0, %1, %2, %0;" : "+l"(d) : "l"(a), "l"(b))
#define PACK2(p, v)   asm("mov.b64 %0, {%1, %2};" : "=l"(p) : "f"(v), "f"(v))
#define UNPACK2(lo, hi, p) asm("mov.b64 {%0, %1}, %2;" : "=f"(lo), "=f"(hi) : "l"(p))

// ---------------- K0: zero scratch ------------------------------------------------
__global__ void k_zero() {
    int i = blockIdx.x * blockDim.x + threadIdx.x;
    if (i <= N_NODES) g_counts[i] = 0;
    if (i == 0) { g_maxhl = 0u; g_maxhr = 0u; g_maxhe = 0u; }
}

// ---------------- K1: histogram of targets ---------------------------------------
__global__ void k_count(const int* __restrict__ edge) {
    int e = blockIdx.x * blockDim.x + threadIdx.x;
    if (e < N_EDGES) atomicAdd(&g_counts[edge[N_EDGES + e]], 1);
}

// ---------------- K2: h = nan_clean(x @ W) + fused hl/hr + maxes ------------------
// BM=128 rows, BN=128 cols (all), BK=16. 256 threads, 8x8 register tile each.
// Epilogue: each row's 128 cols live in lanes (ty fixed, tx 0..15) of one warp;
// head hh = tx>>2 spans 4 lanes -> shuffle reduce gives hl/hr for free.
__global__ __launch_bounds__(256, 2) void k_gemm(const float* __restrict__ x,
                                                 const float* __restrict__ W,
                                                 const float* __restrict__ a_l,
                                                 const float* __restrict__ a_r) {
    __shared__ ull   xs2[128][16];   // x value duplicated into both f32x2 lanes
    __shared__ float ws[16][128];
    const int t  = threadIdx.x;
    const int tx = t & 15;           // col group: cols tx*8 .. tx*8+7
    const int ty = t >> 4;           // 0..15: rows ty + 16*rr
    const int row0 = blockIdx.x * 128;

    ull acc[8][4];
#pragma unroll
    for (int r = 0; r < 8; r++)
#pragma unroll
        for (int c = 0; c < 4; c++) acc[r][c] = 0ull;

    for (int k0 = 0; k0 < IN_H; k0 += 16) {
#pragma unroll
        for (int i = 0; i < 2; i++) {              // 512 float4 x-loads
            int i4 = t + i * 256;
            int r = i4 >> 2, kk4 = i4 & 3;
            int row = row0 + r;
            float4 v = make_float4(0.f, 0.f, 0.f, 0.f);
            if (row < N_NODES)
                v = *(const float4*)(x + (size_t)row * IN_H + k0 + kk4 * 4);
            ull p0, p1, p2, p3;
            PACK2(p0, v.x); PACK2(p1, v.y); PACK2(p2, v.z); PACK2(p3, v.w);
            xs2[r][kk4 * 4 + 0] = p0;
            xs2[r][kk4 * 4 + 1] = p1;
            xs2[r][kk4 * 4 + 2] = p2;
            xs2[r][kk4 * 4 + 3] = p3;
        }
#pragma unroll
        for (int i = 0; i < 2; i++) {              // 512 float4 W-loads
            int i4 = t + i * 256;
            int kk = i4 >> 5, c4 = i4 & 31;
            *(float4*)&ws[kk][c4 * 4] = *(const float4*)(W + (size_t)(k0 + kk) * HDIM + c4 * 4);
        }
        __syncthreads();
#pragma unroll
        for (int kk = 0; kk < 16; kk++) {
            ull b0 = ((const ull*)&ws[kk][0])[tx * 4 + 0];
            ull b1 = ((const ull*)&ws[kk][0])[tx * 4 + 1];
            ull b2 = ((const ull*)&ws[kk][0])[tx * 4 + 2];
            ull b3 = ((const ull*)&ws[kk][0])[tx * 4 + 3];
#pragma unroll
            for (int rr = 0; rr < 8; rr++) {
                ull ax = xs2[ty + 16 * rr][kk];
                FMA2(acc[rr][0], ax, b0);
                FMA2(acc[rr][1], ax, b1);
                FMA2(acc[rr][2], ax, b2);
                FMA2(acc[rr][3], ax, b3);
            }
        }
        __syncthreads();
    }

    // ---- epilogue: store h + fused hl/hr ----
    const int hh  = tx >> 2;         // head of this thread's 8 cols
    const int sub = tx & 3;          // position within head (8 cols each)
    float al[8], ar[8];
    *(float4*)&al[0] = *(const float4*)(a_l + hh * OUT_H + sub * 8);
    *(float4*)&al[4] = *(const float4*)(a_l + hh * OUT_H + sub * 8 + 4);
    *(float4*)&ar[0] = *(const float4*)(a_r + hh * OUT_H + sub * 8);
    *(float4*)&ar[4] = *(const float4*)(a_r + hh * OUT_H + sub * 8 + 4);

    float ml = -CUDART_INF_F, mr = -CUDART_INF_F;
#pragma unroll
    for (int rr = 0; rr < 8; rr++) {
        int row = row0 + ty + 16 * rr;
        float v[8];
#pragma unroll
        for (int j = 0; j < 4; j++) UNPACK2(v[2 * j], v[2 * j + 1], acc[rr][j]);
#pragma unroll
        for (int j = 0; j < 8; j++) v[j] = (v[j] == v[j]) ? v[j] : 0.0f;
        float pl = 0.f, pr = 0.f;
        if (row < N_NODES) {
            *(float4*)(g_h + (size_t)row * HDIM + tx * 8)     = make_float4(v[0], v[1], v[2], v[3]);
            *(float4*)(g_h + (size_t)row * HDIM + tx * 8 + 4) = make_float4(v[4], v[5], v[6], v[7]);
#pragma unroll
            for (int j = 0; j < 8; j++) { pl += v[j] * al[j]; pr += v[j] * ar[j]; }
        }
        // reduce across the 4 lanes of this head (lane bits 0..1 == sub)
        pl += __shfl_xor_sync(0xFFFFFFFFu, pl, 1);
        pl += __shfl_xor_sync(0xFFFFFFFFu, pl, 2);
        pr += __shfl_xor_sync(0xFFFFFFFFu, pr, 1);
        pr += __shfl_xor_sync(0xFFFFFFFFu, pr, 2);
        if (sub == 0 && row < N_NODES) {
            g_hl[row * NHEAD + hh] = pl;
            g_hr[row * NHEAD + hh] = pr;
            ml = fmaxf(ml, pl);
            mr = fmaxf(mr, pr);
        }
    }
    // warp-level max then one atomic per warp
#pragma unroll
    for (int o = 16; o > 0; o >>= 1) {
        ml = fmaxf(ml, __shfl_xor_sync(0xFFFFFFFFu, ml, o));
        mr = fmaxf(mr, __shfl_xor_sync(0xFFFFFFFFu, mr, o));
    }
    if ((t & 31) == 0) {
        if (ml > -CUDART_INF_F) atomicMax(&g_maxhl, enc_f(ml));
        if (mr > -CUDART_INF_F) atomicMax(&g_maxhr, enc_f(mr));
    }
}

// ---------------- K3: he[t,h] = (a_e * (edge_emb @ W_e)).sum(-1) + max ------------
__global__ void k_he(const float* __restrict__ edge_emb, const float* __restrict__ W_e,
                     const float* __restrict__ a_e) {
    __shared__ float emb[EDGE_H];
    __shared__ float part[2];
    int ti = blockIdx.x >> 2;
    int hh = blockIdx.x & 3;
    int de = threadIdx.x;
    if (de < EDGE_H) emb[de] = edge_emb[ti * EDGE_H + de];
    __syncthreads();
    float p = 0.f;
#pragma unroll 8
    for (int k = 0; k < EDGE_H; k++)
        p += emb[k] * W_e[k * (EDGE_H * NHEAD) + hh * EDGE_H + de];
    float v = p * a_e[hh * EDGE_H + de];
#pragma unroll
    for (int o = 16; o > 0; o >>= 1)
        v += __shfl_xor_sync(0xFFFFFFFFu, v, o);
    if ((de & 31) == 0) part[de >> 5] = v;
    __syncthreads();
    if (de == 0) {
        float r = part[0] + part[1];
        g_he[ti * NHEAD + hh] = r;
        atomicMax(&g_maxhe, enc_f(r));
    }
}

// ---------------- K4: exclusive scan of counts -> offsets/cursor ------------------
__global__ void k_scan() {
    const int C = (N_NODES + 1023) / 1024;
    __shared__ int ssum[1024];
    int t = threadIdx.x;
    int beg = t * C;
    int end = min(beg + C, N_NODES);
    int local = 0;
    for (int i = beg; i < end; i++) local += g_counts[i];
    ssum[t] = local;
    __syncthreads();
    for (int d = 1; d < 1024; d <<= 1) {
        int v = (t >= d) ? ssum[t - d] : 0;
        __syncthreads();
        ssum[t] += v;
        __syncthreads();
    }
    int run = (t == 0) ? 0 : ssum[t - 1];
    for (int i = beg; i < end; i++) {
        g_offsets[i] = run;
        g_cursor[i]  = run;
        run += g_counts[i];
    }
    if (t == 1023) g_offsets[N_NODES] = ssum[1023];
}

// ---------------- K5: fused score + exp + CSR scatter + coalesced exp write -------
// softmax shift uses upper bound M = max(hl)+max(hr)+max(he); shift-invariant.
__global__ void k_edge(const int* __restrict__ edge, float* __restrict__ attn) {
    int e = blockIdx.x * blockDim.x + threadIdx.x;
    if (e >= N_EDGES) return;
    float M = dec_f(g_maxhl) + dec_f(g_maxhr) + dec_f(g_maxhe);
    int s  = edge[e];
    int tg = edge[N_EDGES + e];
    int ty = edge[2 * N_EDGES + e];
    float4 hl = *(const float4*)(g_hl + s * 4);
    float4 hr = *(const float4*)(g_hr + tg * 4);
    float4 he = *(const float4*)(g_he + ty * 4);
    float4 sc;
    sc.x = hl.x + hr.x + he.x;  sc.x = sc.x > 0.f ? sc.x : NEG_SLOPE * sc.x;
    sc.y = hl.y + hr.y + he.y;  sc.y = sc.y > 0.f ? sc.y : NEG_SLOPE * sc.y;
    sc.z = hl.z + hr.z + he.z;  sc.z = sc.z > 0.f ? sc.z : NEG_SLOPE * sc.z;
    sc.w = hl.w + hr.w + he.w;  sc.w = sc.w > 0.f ? sc.w : NEG_SLOPE * sc.w;
    float4 ex;
    ex.x = __expf(sc.x - M);
    ex.y = __expf(sc.y - M);
    ex.z = __expf(sc.z - M);
    ex.w = __expf(sc.w - M);
    *(float4*)(attn + (size_t)e * 4) = ex;           // coalesced, normalized later
    int pos = atomicAdd(&g_cursor[tg], 1);
    g_exps[pos]    = ex;
    g_ssorted[pos] = s;
}

// ---------------- K6: CSR aggregation, single pass, warp per target node ----------
// Accumulate unnormalized messages + denominator; scale once at the end.
__global__ void k_agg(float* __restrict__ out) {
    int gw   = (blockIdx.x * blockDim.x + threadIdx.x) >> 5;
    int lane = threadIdx.x & 31;
    if (gw >= N_NODES) return;
    int beg = g_offsets[gw];
    int end = g_offsets[gw + 1];

    float a0 = 0.f, a1 = 0.f, a2 = 0.f, a3 = 0.f;
    float d0 = 0.f, d1 = 0.f, d2 = 0.f, d3 = 0.f;
    for (int i = beg; i < end; i++) {
        float4 ex = g_exps[i];          // broadcast (same addr across warp)
        int s = g_ssorted[i];
        const float* hp = g_h + (size_t)s * HDIM + lane;
        a0 += ex.x * hp[0];
        a1 += ex.y * hp[32];
        a2 += ex.z * hp[64];
        a3 += ex.w * hp[96];
        d0 += ex.x; d1 += ex.y; d2 += ex.z; d3 += ex.w;
    }
    float4 inv;
    inv.x = 1.0f / (d0 + 1e-16f);
    inv.y = 1.0f / (d1 + 1e-16f);
    inv.z = 1.0f / (d2 + 1e-16f);
    inv.w = 1.0f / (d3 + 1e-16f);
    float* op = out + (size_t)gw * HDIM + lane;
    op[0]  = a0 * inv.x;
    op[32] = a1 * inv.y;
    op[64] = a2 * inv.z;
    op[96] = a3 * inv.w;
    if (lane == 0) g_inv[gw] = inv;
}

// ---------------- K7: attn finalize: attn[e] = exp[e] * inv[trg[e]] (coalesced) ---
__global__ void k_attn(const int* __restrict__ edge, float* __restrict__ attn) {
    int e = blockIdx.x * blockDim.x + threadIdx.x;
    if (e >= N_EDGES) return;
    int tg = edge[N_EDGES + e];
    float4 ex  = *(const float4*)(attn + (size_t)e * 4);
    float4 inv = g_inv[tg];
    ex.x *= inv.x; ex.y *= inv.y; ex.z *= inv.z; ex.w *= inv.w;
    *(float4*)(attn + (size_t)e * 4) = ex;
}

// ---------------- launch ----------------------------------------------------------
extern "C" void kernel_launch(void* const* d_in, const int* in_sizes, int n_in,
                              void* d_out, int out_size) {
    const int*   edge     = (const int*)d_in[0];
    const float* x        = (const float*)d_in[1];
    const float* edge_emb = (const float*)d_in[2];
    const float* W        = (const float*)d_in[3];
    const float* W_e      = (const float*)d_in[4];
    const float* a_l      = (const float*)d_in[5];
    const float* a_r      = (const float*)d_in[6];
    const float* a_e      = (const float*)d_in[7];
    float* out  = (float*)d_out;
    float* attn = out + (size_t)N_NODES * HDIM;

    (void)in_sizes; (void)n_in; (void)out_size;

    k_zero <<<(N_NODES + 256) / 256, 256>>>();
    k_count<<<N_EDGES / 256, 256>>>(edge);
    k_gemm <<<(N_NODES + 127) / 128, 256>>>(x, W, a_l, a_r);
    k_he   <<<N_ETYPES * NHEAD, EDGE_H>>>(edge_emb, W_e, a_e);
    k_scan <<<1, 1024>>>();
    k_edge <<<N_EDGES / 256, 256>>>(edge, attn);
    k_agg  <<<(N_NODES * 32 + 255) / 256, 256>>>(out);
    k_attn <<<N_EDGES / 256, 256>>>(edge, attn);
}